// round 8
// baseline (speedup 1.0000x reference)
#include <cuda_runtime.h>
#include <math_constants.h>

// Fixed problem shape: B=16, R=Hr*Wr=4096, Hq*Wq=Q=1024
#define R 4096
#define Q 1024
#define MAXB 16
#define RCHUNK 64
#define NCHUNK (R / RCHUNK)     // 64 chunks per batch
#define NB16 64                 // 64 column-blocks of 16 columns each
#define LOG2E 1.4426950408889634f

// Static device scratch
__device__ float  g_part[NCHUNK * MAXB * Q];                   // 4 MB partial column sums
__device__ float  g_creflog[MAXB * Q];                          // 64 KB log column sums
__device__ float  g_cmin16[MAXB * NB16];                        // per-16col min Cref
__device__ float  g_bm[(size_t)MAXB * R * NB16];                // 16 MB per-row 16-col maxes
__device__ __align__(16) unsigned char g_bi[(size_t)MAXB * R * NB16]; // 4 MB witness idx
__device__ float  g_rs[MAXB * R];                               // row sums of exp(aq*x)

__device__ __forceinline__ float ex2f(float t) {
    float r;
    asm("ex2.approx.ftz.f32 %0, %1;" : "=f"(r) : "f"(t));
    return r;
}

// ---------------------------------------------------------------------------
// Pass 1: stream x once per 64-row chunk; thread t owns columns 4t..4t+3.
// Per row: 16-col block maxes (2-level butterfly) + witness index, 32-col
// partial row sums (3-level butterfly), column-sum partials of exp(ar*x).
// ---------------------------------------------------------------------------
__global__ __launch_bounds__(256) void qatm_pass1(
    const float* __restrict__ x,
    const float* __restrict__ cr,
    const float* __restrict__ cq)
{
    __shared__ float s_bm[RCHUNK * NB16];                       // 16 KB [row][j]
    __shared__ float s_rs32[RCHUNK * 32];                       // 8 KB [row][32colblk]
    __shared__ __align__(16) unsigned char s_bi[RCHUNK * NB16]; // 4 KB [row][j]

    const int b    = blockIdx.x >> 6;
    const int c    = blockIdx.x & (NCHUNK - 1);
    const int t    = threadIdx.x;
    const int lane = t & 31;
    const int g16  = t >> 2;                 // 16-col block 0..63 owned by thread
    const int g32  = t >> 3;                 // 32-col group for row-sum partials
    const int l4   = 4 * (lane & 3);         // base idx of this thread within 16-col blk

    const float ar  = cr[0];
    const float aq  = cq[0];
    const bool same = (ar == aq);
    const float arl = ar * LOG2E;
    const float aql = aq * LOG2E;

    const float4* p = reinterpret_cast<const float4*>(
        x + ((size_t)b * R + (size_t)c * RCHUNK) * Q) + t;

    float4 acc = make_float4(0.f, 0.f, 0.f, 0.f);

    #pragma unroll 1
    for (int r = 0; r < RCHUNK; r += 4) {
        float4 v0 = p[0 * (Q / 4)];
        float4 v1 = p[1 * (Q / 4)];
        float4 v2 = p[2 * (Q / 4)];
        float4 v3 = p[3 * (Q / 4)];
        p += 4 * (Q / 4);

        #pragma unroll
        for (int k = 0; k < 4; ++k) {
            float4 v = (k == 0) ? v0 : (k == 1) ? v1 : (k == 2) ? v2 : v3;

            float e0 = ex2f(arl * v.x);
            float e1 = ex2f(arl * v.y);
            float e2 = ex2f(arl * v.z);
            float e3 = ex2f(arl * v.w);
            acc.x += e0; acc.y += e1; acc.z += e2; acc.w += e3;

            float rsl;
            if (same) {
                rsl = (e0 + e1) + (e2 + e3);
            } else {
                rsl = ex2f(aql * v.x) + ex2f(aql * v.y)
                    + ex2f(aql * v.z) + ex2f(aql * v.w);
            }
            // 3-level butterfly: 8-lane (32-column) row-sum partial
            rsl += __shfl_xor_sync(0xFFFFFFFFu, rsl, 4);
            rsl += __shfl_xor_sync(0xFFFFFFFFu, rsl, 2);
            rsl += __shfl_xor_sync(0xFFFFFFFFu, rsl, 1);

            // 2-level butterfly: 4-lane (16-column) block max
            float mk = fmaxf(fmaxf(v.x, v.y), fmaxf(v.z, v.w));
            mk = fmaxf(mk, __shfl_xor_sync(0xFFFFFFFFu, mk, 2));
            mk = fmaxf(mk, __shfl_xor_sync(0xFFFFFFFFu, mk, 1));

            // witness index within the 16-col block (exact equality holds)
            int idx = -1;
            if (v.x == mk) idx = l4;
            if (v.y == mk) idx = l4 + 1;
            if (v.z == mk) idx = l4 + 2;
            if (v.w == mk) idx = l4 + 3;
            if (idx >= 0) s_bi[(r + k) * NB16 + g16] = (unsigned char)idx;

            if ((lane & 3) == 0) s_bm[(r + k) * NB16 + g16] = mk;
            if ((lane & 7) == 0) s_rs32[(r + k) * 32 + g32] = rsl;
        }
    }
    __syncthreads();

    // partial column sums ([chunk][b][col])
    reinterpret_cast<float4*>(g_part + (size_t)c * (MAXB * Q) + (size_t)b * Q)[t] = acc;

    // finish row sums: thread t<64 sums 32 partials of row t (rotated)
    if (t < RCHUNK) {
        float s = 0.f;
        #pragma unroll
        for (int i = 0; i < 32; ++i)
            s += s_rs32[t * 32 + ((i + t) & 31)];
        g_rs[b * R + c * RCHUNK + t] = s;
    }

    // block maxes (16 KB) + witness indices (4 KB)
    const size_t rowbase = (size_t)b * R + (size_t)c * RCHUNK;
    float4* gbm = reinterpret_cast<float4*>(g_bm + rowbase * NB16);
    const float4* sb = reinterpret_cast<const float4*>(s_bm);
    #pragma unroll
    for (int i = 0; i < 4; ++i)
        gbm[t + 256 * i] = sb[t + 256 * i];
    reinterpret_cast<uint4*>(g_bi + rowbase * NB16)[t] =
        reinterpret_cast<const uint4*>(s_bi)[t];
}

// ---------------------------------------------------------------------------
// Kernel 2: Cref = log(colsum); per-16-column Cmin.
// ---------------------------------------------------------------------------
__global__ __launch_bounds__(256) void qatm_cred()
{
    const int b    = blockIdx.x >> 2;
    const int col  = ((blockIdx.x & 3) << 8) + threadIdx.x;
    const int lane = threadIdx.x & 31;

    const float* p = g_part + (size_t)b * Q + col;
    float s = 0.f;
    #pragma unroll 8
    for (int c = 0; c < NCHUNK; ++c)
        s += p[(size_t)c * (MAXB * Q)];

    float lg = __logf(s);
    g_creflog[b * Q + col] = lg;

    float mn = lg;
    #pragma unroll
    for (int o = 8; o > 0; o >>= 1)
        mn = fminf(mn, __shfl_xor_sync(0xFFFFFFFFu, mn, o));
    if ((lane & 15) == 0)
        g_cmin16[b * NB16 + (col >> 4)] = mn;
}

// ---------------------------------------------------------------------------
// Pass 2: warp per FOUR rows, 64 blocks/row (16 cols each).
//   val_j = cc*bm_j - Cref[witness_j]  (exact, L2 gather)
//   ub_j  = cc*bm_j - Cmin16_j         (true upper bound)
//   lb    = max_j val_j; scan blocks with ub_j > lb, 2 blocks/row/round
//   (half-warp per block), all loads independent.
// ---------------------------------------------------------------------------
__global__ __launch_bounds__(256) void qatm_p2(
    const float* __restrict__ x,
    const float* __restrict__ cr,
    const float* __restrict__ cq,
    float* __restrict__ out)
{
    const int wid  = threadIdx.x >> 5;
    const int lane = threadIdx.x & 31;
    const int row0 = (blockIdx.x * 8 + wid) * 4;
    const int b    = row0 >> 12;           // 4 consecutive rows share a batch

    const float cc  = cr[0] + cq[0];
    const float* cl = g_creflog + (size_t)b * Q;

    const float cminA = __ldg(&g_cmin16[b * NB16 + lane]);
    const float cminB = __ldg(&g_cmin16[b * NB16 + 32 + lane]);

    float bmA[4], bmB[4], cwA[4], cwB[4], m[4];
    int   biA[4], biB[4];
    unsigned long long mask[4];

    #pragma unroll
    for (int r = 0; r < 4; ++r) {
        const size_t base = (size_t)(row0 + r) * NB16;
        bmA[r] = g_bm[base + lane];
        bmB[r] = g_bm[base + 32 + lane];
        biA[r] = (int)g_bi[base + lane];
        biB[r] = (int)g_bi[base + 32 + lane];
    }
    float rr = (lane < 4) ? __ldg(&g_rs[row0 + lane]) : 1.f;

    #pragma unroll
    for (int r = 0; r < 4; ++r) {
        cwA[r] = __ldg(cl + lane * 16 + biA[r]);
        cwB[r] = __ldg(cl + (32 + lane) * 16 + biB[r]);
    }

    #pragma unroll
    for (int r = 0; r < 4; ++r) {
        float vA = fmaf(cc, bmA[r], -cwA[r]);
        float vB = fmaf(cc, bmB[r], -cwB[r]);
        float mm = fmaxf(vA, vB);
        #pragma unroll
        for (int o = 16; o > 0; o >>= 1)
            mm = fmaxf(mm, __shfl_xor_sync(0xFFFFFFFFu, mm, o));
        m[r] = mm;
        unsigned ka = __ballot_sync(0xFFFFFFFFu, fmaf(cc, bmA[r], -cminA) > mm);
        unsigned kb = __ballot_sync(0xFFFFFFFFu, fmaf(cc, bmB[r], -cminB) > mm);
        mask[r] = (unsigned long long)ka | ((unsigned long long)kb << 32);
    }

    const int half = lane >> 4;        // 0 or 1: which survivor this lane serves
    const int l16  = lane & 15;

    while (mask[0] | mask[1] | mask[2] | mask[3]) {
        int j[4];
        #pragma unroll
        for (int r = 0; r < 4; ++r) {
            int j0 = -1, j1 = -1;
            if (mask[r]) { j0 = __ffsll(mask[r]) - 1; mask[r] &= mask[r] - 1; }
            if (mask[r]) { j1 = __ffsll(mask[r]) - 1; mask[r] &= mask[r] - 1; }
            j[r] = half ? j1 : j0;
        }
        float a[4], cf[4];
        #pragma unroll
        for (int r = 0; r < 4; ++r) {
            a[r]  = (j[r] >= 0) ? __ldcs(x + (size_t)(row0 + r) * Q + j[r] * 16 + l16) : 0.f;
            cf[r] = (j[r] >= 0) ? __ldg(cl + j[r] * 16 + l16) : 0.f;
        }
        #pragma unroll
        for (int r = 0; r < 4; ++r)
            if (j[r] >= 0) m[r] = fmaxf(m[r], fmaf(cc, a[r], -cf[r]));
    }

    #pragma unroll
    for (int r = 0; r < 4; ++r) {
        #pragma unroll
        for (int o = 16; o > 0; o >>= 1)
            m[r] = fmaxf(m[r], __shfl_xor_sync(0xFFFFFFFFu, m[r], o));
    }

    if (lane < 4) {
        float mm = (lane == 0) ? m[0] : (lane == 1) ? m[1] : (lane == 2) ? m[2] : m[3];
        out[row0 + lane] = __expf(0.5f * (mm - __logf(rr)));
    }
}

// ---------------------------------------------------------------------------
extern "C" void kernel_launch(void* const* d_in, const int* in_sizes, int n_in,
                              void* d_out, int out_size)
{
    const float* x  = (const float*)d_in[0];
    const float* cr = (const float*)d_in[1];
    const float* cq = (const float*)d_in[2];
    float* out = (float*)d_out;

    const int B = in_sizes[0] / (R * Q);   // 16

    qatm_pass1<<<B * NCHUNK, 256>>>(x, cr, cq);
    qatm_cred<<<B * 4, 256>>>();
    qatm_p2<<<B * R / 32, 256>>>(x, cr, cq, out);
}

// round 9
// speedup vs baseline: 1.0866x; 1.0866x over previous
#include <cuda_runtime.h>
#include <math_constants.h>

// Fixed problem shape: B=16, R=Hr*Wr=4096, Q=Hq*Wq=1024
#define R 4096
#define Q 1024
#define MAXB 16
#define RCHUNK 64
#define NCHUNK (R / RCHUNK)     // 64 chunks per batch
#define NBLK 32                 // 32 column-blocks of 32 columns each
#define LOG2E 1.4426950408889634f

// Static device scratch
__device__ float  g_part[NCHUNK * MAXB * Q];                 // 4 MB partial column sums
__device__ float  g_creflog[MAXB * Q];                        // 64 KB log column sums
__device__ float  g_cmin[MAXB * NBLK];                        // per-32col min Cref
__device__ float  g_bm[(size_t)MAXB * R * NBLK];              // 8 MB per-row 32-col maxes
__device__ __align__(16) unsigned char g_bi[(size_t)MAXB * R * NBLK];  // 2 MB witness idx
__device__ float  g_rs[MAXB * R];                             // row sums of exp(aq*x)

__device__ __forceinline__ float ex2f(float t) {
    float r;
    asm("ex2.approx.ftz.f32 %0, %1;" : "=f"(r) : "f"(t));
    return r;
}

// ---------------------------------------------------------------------------
// Pass 1: stream x once per 64-row chunk; thread t owns columns 4t..4t+3.
// 8 rows in flight per iteration (MLP 8), x loaded with __ldcg (L2-only:
// every line is touched exactly once by one thread — L1 would be pollution).
// exp via single FMUL (alpha*log2e folded) + ex2. Row sums reduced to 8-lane
// (32-column) partials in the same butterfly as the block max; a 64-thread
// epilogue finishes them from smem.
// ---------------------------------------------------------------------------
__global__ __launch_bounds__(256) void qatm_pass1(
    const float* __restrict__ x,
    const float* __restrict__ cr,
    const float* __restrict__ cq)
{
    __shared__ float s_bm[RCHUNK * NBLK];                      // 8 KB [row][j]
    __shared__ float s_rs32[RCHUNK * NBLK];                    // 8 KB [row][j] partial rs
    __shared__ __align__(8) unsigned char s_bi[RCHUNK * NBLK]; // 2 KB [row][j]

    const int b    = blockIdx.x >> 6;
    const int c    = blockIdx.x & (NCHUNK - 1);
    const int t    = threadIdx.x;
    const int lane = t & 31;
    const int g    = t >> 3;                 // column-block 0..31 owned by thread
    const int l8   = 4 * (lane & 7);         // base idx of this thread within block

    const float ar  = cr[0];
    const float aq  = cq[0];
    const bool same = (ar == aq);
    const float arl = ar * LOG2E;
    const float aql = aq * LOG2E;

    const float4* p = reinterpret_cast<const float4*>(
        x + ((size_t)b * R + (size_t)c * RCHUNK) * Q) + t;

    float4 acc = make_float4(0.f, 0.f, 0.f, 0.f);

    #pragma unroll 1
    for (int r = 0; r < RCHUNK; r += 8) {
        // 8 independent 128B loads in flight before any consumption
        float4 v[8];
        #pragma unroll
        for (int k = 0; k < 8; ++k)
            v[k] = __ldcg(p + k * (Q / 4));
        p += 8 * (Q / 4);

        #pragma unroll
        for (int k = 0; k < 8; ++k) {
            float4 w = v[k];

            float e0 = ex2f(arl * w.x);
            float e1 = ex2f(arl * w.y);
            float e2 = ex2f(arl * w.z);
            float e3 = ex2f(arl * w.w);
            acc.x += e0; acc.y += e1; acc.z += e2; acc.w += e3;

            float rsl;
            if (same) {
                rsl = (e0 + e1) + (e2 + e3);
            } else {
                rsl = ex2f(aql * w.x) + ex2f(aql * w.y)
                    + ex2f(aql * w.z) + ex2f(aql * w.w);
            }

            float mk = fmaxf(fmaxf(w.x, w.y), fmaxf(w.z, w.w));

            // shared 3-level butterfly over the 8-lane group (32 columns)
            #pragma unroll
            for (int o = 4; o > 0; o >>= 1) {
                rsl += __shfl_xor_sync(0xFFFFFFFFu, rsl, o);
                mk = fmaxf(mk, __shfl_xor_sync(0xFFFFFFFFu, mk, o));
            }

            // witness index: some lane's component equals mk exactly
            int idx = -1;
            if (w.x == mk) idx = l8;
            if (w.y == mk) idx = l8 + 1;
            if (w.z == mk) idx = l8 + 2;
            if (w.w == mk) idx = l8 + 3;
            if (idx >= 0) s_bi[(r + k) * NBLK + g] = (unsigned char)idx;

            if ((lane & 7) == 0) {
                s_bm[(r + k) * NBLK + g]   = mk;
                s_rs32[(r + k) * NBLK + g] = rsl;
            }
        }
    }
    __syncthreads();

    // partial column sums ([chunk][b][col])
    reinterpret_cast<float4*>(g_part + (size_t)c * (MAXB * Q) + (size_t)b * Q)[t] = acc;

    // finish row sums: thread t<64 sums 32 partials of row t (rotated, no conflicts)
    if (t < RCHUNK) {
        float s = 0.f;
        #pragma unroll
        for (int i = 0; i < NBLK; ++i)
            s += s_rs32[t * NBLK + ((i + t) & (NBLK - 1))];
        g_rs[b * R + c * RCHUNK + t] = s;
    }

    // block maxes (8 KB) + witness indices (2 KB)
    const size_t rowbase = (size_t)b * R + (size_t)c * RCHUNK;
    float4* gbm = reinterpret_cast<float4*>(g_bm + rowbase * NBLK);
    const float4* sb = reinterpret_cast<const float4*>(s_bm);
    gbm[t]       = sb[t];
    gbm[t + 256] = sb[t + 256];
    reinterpret_cast<uint2*>(g_bi + rowbase * NBLK)[t] =
        reinterpret_cast<const uint2*>(s_bi)[t];
}

// ---------------------------------------------------------------------------
// Kernel 2: Cref = log(colsum); per-32-column Cmin.
// ---------------------------------------------------------------------------
__global__ __launch_bounds__(256) void qatm_cred()
{
    const int b    = blockIdx.x >> 2;
    const int col  = ((blockIdx.x & 3) << 8) + threadIdx.x;
    const int lane = threadIdx.x & 31;

    const float* p = g_part + (size_t)b * Q + col;
    float s = 0.f;
    #pragma unroll 8
    for (int c = 0; c < NCHUNK; ++c)
        s += p[(size_t)c * (MAXB * Q)];

    float lg = __logf(s);
    g_creflog[b * Q + col] = lg;

    float mn = lg;
    #pragma unroll
    for (int o = 16; o > 0; o >>= 1)
        mn = fminf(mn, __shfl_xor_sync(0xFFFFFFFFu, mn, o));
    if (lane == 0)
        g_cmin[b * NBLK + (col >> 5)] = mn;
}

// ---------------------------------------------------------------------------
// Pass 2 (unchanged from R7): warp per FOUR rows — all header loads issued
// independently up front (MLP ~8), joint survivor drain across the 4 masks.
// ---------------------------------------------------------------------------
__global__ __launch_bounds__(256) void qatm_p2(
    const float* __restrict__ x,
    const float* __restrict__ cr,
    const float* __restrict__ cq,
    float* __restrict__ out)
{
    const int wid  = threadIdx.x >> 5;
    const int lane = threadIdx.x & 31;
    const int row0 = (blockIdx.x * 8 + wid) * 4;
    const int b    = row0 >> 12;           // 4 consecutive rows share a batch

    const float cc = cr[0] + cq[0];
    const float* cl = g_creflog + (size_t)b * Q;

    // independent header loads for 4 rows
    const float cmin = __ldg(&g_cmin[b * NBLK + lane]);
    float bm0 = g_bm[(size_t)(row0 + 0) * NBLK + lane];
    float bm1 = g_bm[(size_t)(row0 + 1) * NBLK + lane];
    float bm2 = g_bm[(size_t)(row0 + 2) * NBLK + lane];
    float bm3 = g_bm[(size_t)(row0 + 3) * NBLK + lane];
    int bi0 = (int)g_bi[(size_t)(row0 + 0) * NBLK + lane];
    int bi1 = (int)g_bi[(size_t)(row0 + 1) * NBLK + lane];
    int bi2 = (int)g_bi[(size_t)(row0 + 2) * NBLK + lane];
    int bi3 = (int)g_bi[(size_t)(row0 + 3) * NBLK + lane];
    float rr = (lane < 4) ? __ldg(&g_rs[row0 + lane]) : 1.f;

    float cw0 = __ldg(cl + lane * 32 + bi0);
    float cw1 = __ldg(cl + lane * 32 + bi1);
    float cw2 = __ldg(cl + lane * 32 + bi2);
    float cw3 = __ldg(cl + lane * 32 + bi3);

    float ub0 = fmaf(cc, bm0, -cmin), v0 = fmaf(cc, bm0, -cw0);
    float ub1 = fmaf(cc, bm1, -cmin), v1 = fmaf(cc, bm1, -cw1);
    float ub2 = fmaf(cc, bm2, -cmin), v2 = fmaf(cc, bm2, -cw2);
    float ub3 = fmaf(cc, bm3, -cmin), v3 = fmaf(cc, bm3, -cw3);

    float m0 = v0, m1 = v1, m2 = v2, m3 = v3;
    #pragma unroll
    for (int o = 16; o > 0; o >>= 1) {
        m0 = fmaxf(m0, __shfl_xor_sync(0xFFFFFFFFu, m0, o));
        m1 = fmaxf(m1, __shfl_xor_sync(0xFFFFFFFFu, m1, o));
        m2 = fmaxf(m2, __shfl_xor_sync(0xFFFFFFFFu, m2, o));
        m3 = fmaxf(m3, __shfl_xor_sync(0xFFFFFFFFu, m3, o));
    }

    unsigned k0 = __ballot_sync(0xFFFFFFFFu, ub0 > m0);
    unsigned k1 = __ballot_sync(0xFFFFFFFFu, ub1 > m1);
    unsigned k2 = __ballot_sync(0xFFFFFFFFu, ub2 > m2);
    unsigned k3 = __ballot_sync(0xFFFFFFFFu, ub3 > m3);

    const float* px0 = x + (size_t)(row0 + 0) * Q;
    const float* px1 = x + (size_t)(row0 + 1) * Q;
    const float* px2 = x + (size_t)(row0 + 2) * Q;
    const float* px3 = x + (size_t)(row0 + 3) * Q;

    while (k0 | k1 | k2 | k3) {
        int j0 = -1, j1 = -1, j2 = -1, j3 = -1;
        if (k0) { j0 = __ffs(k0) - 1; k0 &= k0 - 1; }
        if (k1) { j1 = __ffs(k1) - 1; k1 &= k1 - 1; }
        if (k2) { j2 = __ffs(k2) - 1; k2 &= k2 - 1; }
        if (k3) { j3 = __ffs(k3) - 1; k3 &= k3 - 1; }

        // all loads issued before any consuming max (MLP up to 8)
        float a0 = (j0 >= 0) ? __ldcs(px0 + j0 * 32 + lane) : 0.f;
        float a1 = (j1 >= 0) ? __ldcs(px1 + j1 * 32 + lane) : 0.f;
        float a2 = (j2 >= 0) ? __ldcs(px2 + j2 * 32 + lane) : 0.f;
        float a3 = (j3 >= 0) ? __ldcs(px3 + j3 * 32 + lane) : 0.f;
        float c0 = (j0 >= 0) ? __ldg(cl + j0 * 32 + lane) : 0.f;
        float c1 = (j1 >= 0) ? __ldg(cl + j1 * 32 + lane) : 0.f;
        float c2 = (j2 >= 0) ? __ldg(cl + j2 * 32 + lane) : 0.f;
        float c3 = (j3 >= 0) ? __ldg(cl + j3 * 32 + lane) : 0.f;

        if (j0 >= 0) m0 = fmaxf(m0, fmaf(cc, a0, -c0));
        if (j1 >= 0) m1 = fmaxf(m1, fmaf(cc, a1, -c1));
        if (j2 >= 0) m2 = fmaxf(m2, fmaf(cc, a2, -c2));
        if (j3 >= 0) m3 = fmaxf(m3, fmaf(cc, a3, -c3));
    }

    #pragma unroll
    for (int o = 16; o > 0; o >>= 1) {
        m0 = fmaxf(m0, __shfl_xor_sync(0xFFFFFFFFu, m0, o));
        m1 = fmaxf(m1, __shfl_xor_sync(0xFFFFFFFFu, m1, o));
        m2 = fmaxf(m2, __shfl_xor_sync(0xFFFFFFFFu, m2, o));
        m3 = fmaxf(m3, __shfl_xor_sync(0xFFFFFFFFu, m3, o));
    }

    if (lane < 4) {
        float mm = (lane == 0) ? m0 : (lane == 1) ? m1 : (lane == 2) ? m2 : m3;
        out[row0 + lane] = __expf(0.5f * (mm - __logf(rr)));
    }
}

// ---------------------------------------------------------------------------
extern "C" void kernel_launch(void* const* d_in, const int* in_sizes, int n_in,
                              void* d_out, int out_size)
{
    const float* x  = (const float*)d_in[0];
    const float* cr = (const float*)d_in[1];
    const float* cq = (const float*)d_in[2];
    float* out = (float*)d_out;

    const int B = in_sizes[0] / (R * Q);   // 16

    qatm_pass1<<<B * NCHUNK, 256>>>(x, cr, cq);
    qatm_cred<<<B * 4, 256>>>();
    qatm_p2<<<B * R / 32, 256>>>(x, cr, cq, out);
}

// round 10
// speedup vs baseline: 1.1173x; 1.0282x over previous
#include <cuda_runtime.h>
#include <math_constants.h>

// Fixed problem shape: B=16, R=Hr*Wr=4096, Q=Hq*Wq=1024
#define R 4096
#define Q 1024
#define MAXB 16
#define RCHUNK 64
#define NCHUNK (R / RCHUNK)     // 64 chunks per batch
#define NBLK 32                 // 32 column-blocks of 32 columns each
#define LOG2E 1.4426950408889634f

// Static device scratch
__device__ float  g_part[NCHUNK * MAXB * Q];                 // 4 MB partial column sums
__device__ float  g_creflog[MAXB * Q];                        // 64 KB log column sums
__device__ float  g_cmin[MAXB * NBLK];                        // per-32col min Cref
__device__ float  g_bm[(size_t)MAXB * R * NBLK];              // 8 MB per-row block max (top-1)
__device__ float  g_bm2[(size_t)MAXB * R * NBLK];             // 8 MB per-row block 2nd max
__device__ __align__(16) unsigned char g_bi[(size_t)MAXB * R * NBLK];  // 2 MB witness idx
__device__ float  g_rs[MAXB * R];                             // row sums of exp(aq*x)

__device__ __forceinline__ float ex2f(float t) {
    float r;
    asm("ex2.approx.ftz.f32 %0, %1;" : "=f"(r) : "f"(t));
    return r;
}

// ---------------------------------------------------------------------------
// Pass 1: stream x once per 64-row chunk; thread t owns columns 4t..4t+3.
// 8 rows in flight (MLP 8), x via __ldcg. Per 32-col block: TOP-2 maxes
// (m1 with witness index, m2 value) + 32-col partial row sums, all in one
// shared 3-level butterfly. Column-sum partials of exp(ar*x) as before.
// ---------------------------------------------------------------------------
__global__ __launch_bounds__(256) void qatm_pass1(
    const float* __restrict__ x,
    const float* __restrict__ cr,
    const float* __restrict__ cq)
{
    __shared__ float s_bm[RCHUNK * NBLK];                      // 8 KB [row][j] top-1
    __shared__ float s_bm2[RCHUNK * NBLK];                     // 8 KB [row][j] top-2
    __shared__ float s_rs32[RCHUNK * NBLK];                    // 8 KB [row][j] partial rs
    __shared__ __align__(8) unsigned char s_bi[RCHUNK * NBLK]; // 2 KB [row][j]

    const int b    = blockIdx.x >> 6;
    const int c    = blockIdx.x & (NCHUNK - 1);
    const int t    = threadIdx.x;
    const int lane = t & 31;
    const int g    = t >> 3;                 // column-block 0..31 owned by thread
    const int l8   = 4 * (lane & 7);         // base idx of this thread within block

    const float ar  = cr[0];
    const float aq  = cq[0];
    const bool same = (ar == aq);
    const float arl = ar * LOG2E;
    const float aql = aq * LOG2E;

    const float4* p = reinterpret_cast<const float4*>(
        x + ((size_t)b * R + (size_t)c * RCHUNK) * Q) + t;

    float4 acc = make_float4(0.f, 0.f, 0.f, 0.f);

    #pragma unroll 1
    for (int r = 0; r < RCHUNK; r += 8) {
        float4 v[8];
        #pragma unroll
        for (int k = 0; k < 8; ++k)
            v[k] = __ldcg(p + k * (Q / 4));
        p += 8 * (Q / 4);

        #pragma unroll
        for (int k = 0; k < 8; ++k) {
            float4 w = v[k];

            float e0 = ex2f(arl * w.x);
            float e1 = ex2f(arl * w.y);
            float e2 = ex2f(arl * w.z);
            float e3 = ex2f(arl * w.w);
            acc.x += e0; acc.y += e1; acc.z += e2; acc.w += e3;

            float rsl;
            if (same) {
                rsl = (e0 + e1) + (e2 + e3);
            } else {
                rsl = ex2f(aql * w.x) + ex2f(aql * w.y)
                    + ex2f(aql * w.z) + ex2f(aql * w.w);
            }

            // per-thread top-2 of the 4 components
            float hi1 = fmaxf(w.x, w.y), lo1 = fminf(w.x, w.y);
            float hi2 = fmaxf(w.z, w.w), lo2 = fminf(w.z, w.w);
            float m1 = fmaxf(hi1, hi2);
            float m2 = fmaxf(fminf(hi1, hi2), fmaxf(lo1, lo2));

            // shared 3-level butterfly over the 8-lane group (32 columns):
            // row-sum partial + exact top-2 merge
            #pragma unroll
            for (int o = 4; o > 0; o >>= 1) {
                rsl += __shfl_xor_sync(0xFFFFFFFFu, rsl, o);
                float om1 = __shfl_xor_sync(0xFFFFFFFFu, m1, o);
                float om2 = __shfl_xor_sync(0xFFFFFFFFu, m2, o);
                m2 = fmaxf(fminf(m1, om1), fmaxf(m2, om2));
                m1 = fmaxf(m1, om1);
            }

            // witness index: some lane's component equals m1 exactly
            int idx = -1;
            if (w.x == m1) idx = l8;
            if (w.y == m1) idx = l8 + 1;
            if (w.z == m1) idx = l8 + 2;
            if (w.w == m1) idx = l8 + 3;
            if (idx >= 0) s_bi[(r + k) * NBLK + g] = (unsigned char)idx;

            if ((lane & 7) == 0) {
                s_bm[(r + k) * NBLK + g]   = m1;
                s_bm2[(r + k) * NBLK + g]  = m2;
                s_rs32[(r + k) * NBLK + g] = rsl;
            }
        }
    }
    __syncthreads();

    // partial column sums ([chunk][b][col])
    reinterpret_cast<float4*>(g_part + (size_t)c * (MAXB * Q) + (size_t)b * Q)[t] = acc;

    // finish row sums: thread t<64 sums 32 partials of row t (rotated)
    if (t < RCHUNK) {
        float s = 0.f;
        #pragma unroll
        for (int i = 0; i < NBLK; ++i)
            s += s_rs32[t * NBLK + ((i + t) & (NBLK - 1))];
        g_rs[b * R + c * RCHUNK + t] = s;
    }

    // headers out
    const size_t rowbase = (size_t)b * R + (size_t)c * RCHUNK;
    float4* gbm  = reinterpret_cast<float4*>(g_bm  + rowbase * NBLK);
    float4* gbm2 = reinterpret_cast<float4*>(g_bm2 + rowbase * NBLK);
    const float4* sb  = reinterpret_cast<const float4*>(s_bm);
    const float4* sb2 = reinterpret_cast<const float4*>(s_bm2);
    gbm[t]        = sb[t];
    gbm[t + 256]  = sb[t + 256];
    gbm2[t]       = sb2[t];
    gbm2[t + 256] = sb2[t + 256];
    reinterpret_cast<uint2*>(g_bi + rowbase * NBLK)[t] =
        reinterpret_cast<const uint2*>(s_bi)[t];
}

// ---------------------------------------------------------------------------
// Kernel 2: Cref = log(colsum); per-32-column Cmin.
// ---------------------------------------------------------------------------
__global__ __launch_bounds__(256) void qatm_cred()
{
    const int b    = blockIdx.x >> 2;
    const int col  = ((blockIdx.x & 3) << 8) + threadIdx.x;
    const int lane = threadIdx.x & 31;

    const float* p = g_part + (size_t)b * Q + col;
    float s = 0.f;
    #pragma unroll 8
    for (int c = 0; c < NCHUNK; ++c)
        s += p[(size_t)c * (MAXB * Q)];

    float lg = __logf(s);
    g_creflog[b * Q + col] = lg;

    float mn = lg;
    #pragma unroll
    for (int o = 16; o > 0; o >>= 1)
        mn = fminf(mn, __shfl_xor_sync(0xFFFFFFFFu, mn, o));
    if (lane == 0)
        g_cmin[b * NBLK + (col >> 5)] = mn;
}

// ---------------------------------------------------------------------------
// Pass 2: warp per FOUR rows. Exact bound:
//   lb   = max_j (cc*bm_j - Cref[witness_j])   (witness value is exact)
//   block j needs an x scan ONLY if cc*bm2_j - Cmin_j > lb, because every
//   non-witness element of block j is <= bm2_j (second max) by definition.
// ---------------------------------------------------------------------------
__global__ __launch_bounds__(256) void qatm_p2(
    const float* __restrict__ x,
    const float* __restrict__ cr,
    const float* __restrict__ cq,
    float* __restrict__ out)
{
    const int wid  = threadIdx.x >> 5;
    const int lane = threadIdx.x & 31;
    const int row0 = (blockIdx.x * 8 + wid) * 4;
    const int b    = row0 >> 12;           // 4 consecutive rows share a batch

    const float cc = cr[0] + cq[0];
    const float* cl = g_creflog + (size_t)b * Q;

    // independent header loads for 4 rows
    const float cmin = __ldg(&g_cmin[b * NBLK + lane]);
    float bm0  = g_bm [(size_t)(row0 + 0) * NBLK + lane];
    float bm1  = g_bm [(size_t)(row0 + 1) * NBLK + lane];
    float bm2  = g_bm [(size_t)(row0 + 2) * NBLK + lane];
    float bm3  = g_bm [(size_t)(row0 + 3) * NBLK + lane];
    float s0   = g_bm2[(size_t)(row0 + 0) * NBLK + lane];
    float s1   = g_bm2[(size_t)(row0 + 1) * NBLK + lane];
    float s2   = g_bm2[(size_t)(row0 + 2) * NBLK + lane];
    float s3   = g_bm2[(size_t)(row0 + 3) * NBLK + lane];
    int bi0 = (int)g_bi[(size_t)(row0 + 0) * NBLK + lane];
    int bi1 = (int)g_bi[(size_t)(row0 + 1) * NBLK + lane];
    int bi2 = (int)g_bi[(size_t)(row0 + 2) * NBLK + lane];
    int bi3 = (int)g_bi[(size_t)(row0 + 3) * NBLK + lane];
    float rr = (lane < 4) ? __ldg(&g_rs[row0 + lane]) : 1.f;

    float cw0 = __ldg(cl + lane * 32 + bi0);
    float cw1 = __ldg(cl + lane * 32 + bi1);
    float cw2 = __ldg(cl + lane * 32 + bi2);
    float cw3 = __ldg(cl + lane * 32 + bi3);

    // exact witness values -> lb ; second-max upper bounds -> survivors
    float m0 = fmaf(cc, bm0, -cw0);
    float m1 = fmaf(cc, bm1, -cw1);
    float m2 = fmaf(cc, bm2, -cw2);
    float m3 = fmaf(cc, bm3, -cw3);
    #pragma unroll
    for (int o = 16; o > 0; o >>= 1) {
        m0 = fmaxf(m0, __shfl_xor_sync(0xFFFFFFFFu, m0, o));
        m1 = fmaxf(m1, __shfl_xor_sync(0xFFFFFFFFu, m1, o));
        m2 = fmaxf(m2, __shfl_xor_sync(0xFFFFFFFFu, m2, o));
        m3 = fmaxf(m3, __shfl_xor_sync(0xFFFFFFFFu, m3, o));
    }

    unsigned k0 = __ballot_sync(0xFFFFFFFFu, fmaf(cc, s0, -cmin) > m0);
    unsigned k1 = __ballot_sync(0xFFFFFFFFu, fmaf(cc, s1, -cmin) > m1);
    unsigned k2 = __ballot_sync(0xFFFFFFFFu, fmaf(cc, s2, -cmin) > m2);
    unsigned k3 = __ballot_sync(0xFFFFFFFFu, fmaf(cc, s3, -cmin) > m3);

    const float* px0 = x + (size_t)(row0 + 0) * Q;
    const float* px1 = x + (size_t)(row0 + 1) * Q;
    const float* px2 = x + (size_t)(row0 + 2) * Q;
    const float* px3 = x + (size_t)(row0 + 3) * Q;

    while (k0 | k1 | k2 | k3) {
        int j0 = -1, j1 = -1, j2 = -1, j3 = -1;
        if (k0) { j0 = __ffs(k0) - 1; k0 &= k0 - 1; }
        if (k1) { j1 = __ffs(k1) - 1; k1 &= k1 - 1; }
        if (k2) { j2 = __ffs(k2) - 1; k2 &= k2 - 1; }
        if (k3) { j3 = __ffs(k3) - 1; k3 &= k3 - 1; }

        float a0 = (j0 >= 0) ? __ldcs(px0 + j0 * 32 + lane) : 0.f;
        float a1 = (j1 >= 0) ? __ldcs(px1 + j1 * 32 + lane) : 0.f;
        float a2 = (j2 >= 0) ? __ldcs(px2 + j2 * 32 + lane) : 0.f;
        float a3 = (j3 >= 0) ? __ldcs(px3 + j3 * 32 + lane) : 0.f;
        float c0 = (j0 >= 0) ? __ldg(cl + j0 * 32 + lane) : 0.f;
        float c1 = (j1 >= 0) ? __ldg(cl + j1 * 32 + lane) : 0.f;
        float c2 = (j2 >= 0) ? __ldg(cl + j2 * 32 + lane) : 0.f;
        float c3 = (j3 >= 0) ? __ldg(cl + j3 * 32 + lane) : 0.f;

        if (j0 >= 0) m0 = fmaxf(m0, fmaf(cc, a0, -c0));
        if (j1 >= 0) m1 = fmaxf(m1, fmaf(cc, a1, -c1));
        if (j2 >= 0) m2 = fmaxf(m2, fmaf(cc, a2, -c2));
        if (j3 >= 0) m3 = fmaxf(m3, fmaf(cc, a3, -c3));
    }

    #pragma unroll
    for (int o = 16; o > 0; o >>= 1) {
        m0 = fmaxf(m0, __shfl_xor_sync(0xFFFFFFFFu, m0, o));
        m1 = fmaxf(m1, __shfl_xor_sync(0xFFFFFFFFu, m1, o));
        m2 = fmaxf(m2, __shfl_xor_sync(0xFFFFFFFFu, m2, o));
        m3 = fmaxf(m3, __shfl_xor_sync(0xFFFFFFFFu, m3, o));
    }

    if (lane < 4) {
        float mm = (lane == 0) ? m0 : (lane == 1) ? m1 : (lane == 2) ? m2 : m3;
        out[row0 + lane] = __expf(0.5f * (mm - __logf(rr)));
    }
}

// ---------------------------------------------------------------------------
extern "C" void kernel_launch(void* const* d_in, const int* in_sizes, int n_in,
                              void* d_out, int out_size)
{
    const float* x  = (const float*)d_in[0];
    const float* cr = (const float*)d_in[1];
    const float* cq = (const float*)d_in[2];
    float* out = (float*)d_out;

    const int B = in_sizes[0] / (R * Q);   // 16

    qatm_pass1<<<B * NCHUNK, 256>>>(x, cr, cq);
    qatm_cred<<<B * 4, 256>>>();
    qatm_p2<<<B * R / 32, 256>>>(x, cr, cq, out);
}

// round 11
// speedup vs baseline: 1.1471x; 1.0267x over previous
#include <cuda_runtime.h>
#include <math_constants.h>

// Fixed problem shape: B=16, R=Hr*Wr=4096, Q=Hq*Wq=1024
#define R 4096
#define Q 1024
#define MAXB 16
#define RCHUNK 64
#define NCHUNK (R / RCHUNK)     // 64 chunks per batch
#define NBLK 32                 // 32 column-blocks of 32 columns each
#define LOG2E 1.4426950408889634f
#define M2SCALE 32.0f
#define M2INV   0.03125f

// Static device scratch
__device__ float  g_colsum[MAXB * Q];                         // 64 KB atomic column sums
__device__ float  g_creflog[MAXB * Q];                        // 64 KB log column sums
__device__ float  g_cmin[MAXB * NBLK];                        // per-32col min Cref
__device__ float  g_bm[(size_t)MAXB * R * NBLK];              // 8 MB per-row block max (exact)
__device__ unsigned short g_aux[(size_t)MAXB * R * NBLK];     // 4 MB packed (d<<8)|witness
__device__ float  g_rs[MAXB * R];                             // row sums of exp(aq*x)

__device__ __forceinline__ float ex2f(float t) {
    float r;
    asm("ex2.approx.ftz.f32 %0, %1;" : "=f"(r) : "f"(t));
    return r;
}

// ---------------------------------------------------------------------------
// Zero the atomic column-sum buffer (runs before pass1 each launch).
// ---------------------------------------------------------------------------
__global__ void qatm_zero()
{
    g_colsum[blockIdx.x * 1024 + threadIdx.x] = 0.f;
}

// ---------------------------------------------------------------------------
// Pass 1: stream x once per 64-row chunk; thread t owns columns 4t..4t+3.
// 8 rows in flight (MLP 8), x via __ldcg. Per 32-col block: TOP-2 maxes
// (m1 with witness index, m2 value) + 32-col partial row sums, one shared
// 3-level butterfly. Column sums leave via red.global.add (L2-resident).
// ---------------------------------------------------------------------------
__global__ __launch_bounds__(256) void qatm_pass1(
    const float* __restrict__ x,
    const float* __restrict__ cr,
    const float* __restrict__ cq)
{
    __shared__ float s_bm[RCHUNK * NBLK];                      // 8 KB [row][j] top-1
    __shared__ float s_bm2[RCHUNK * NBLK];                     // 8 KB [row][j] top-2
    __shared__ float s_rs32[RCHUNK * NBLK];                    // 8 KB [row][j] partial rs
    __shared__ __align__(8) unsigned char s_bi[RCHUNK * NBLK]; // 2 KB [row][j]

    const int b    = blockIdx.x >> 6;
    const int c    = blockIdx.x & (NCHUNK - 1);
    const int t    = threadIdx.x;
    const int lane = t & 31;
    const int g    = t >> 3;                 // column-block 0..31 owned by thread
    const int l8   = 4 * (lane & 7);         // base idx of this thread within block

    const float ar  = cr[0];
    const float aq  = cq[0];
    const bool same = (ar == aq);
    const float arl = ar * LOG2E;
    const float aql = aq * LOG2E;

    const float4* p = reinterpret_cast<const float4*>(
        x + ((size_t)b * R + (size_t)c * RCHUNK) * Q) + t;

    float4 acc = make_float4(0.f, 0.f, 0.f, 0.f);

    #pragma unroll 1
    for (int r = 0; r < RCHUNK; r += 8) {
        float4 v[8];
        #pragma unroll
        for (int k = 0; k < 8; ++k)
            v[k] = __ldcg(p + k * (Q / 4));
        p += 8 * (Q / 4);

        #pragma unroll
        for (int k = 0; k < 8; ++k) {
            float4 w = v[k];

            float e0 = ex2f(arl * w.x);
            float e1 = ex2f(arl * w.y);
            float e2 = ex2f(arl * w.z);
            float e3 = ex2f(arl * w.w);
            acc.x += e0; acc.y += e1; acc.z += e2; acc.w += e3;

            float rsl;
            if (same) {
                rsl = (e0 + e1) + (e2 + e3);
            } else {
                rsl = ex2f(aql * w.x) + ex2f(aql * w.y)
                    + ex2f(aql * w.z) + ex2f(aql * w.w);
            }

            // per-thread top-2 of the 4 components
            float hi1 = fmaxf(w.x, w.y), lo1 = fminf(w.x, w.y);
            float hi2 = fmaxf(w.z, w.w), lo2 = fminf(w.z, w.w);
            float m1 = fmaxf(hi1, hi2);
            float m2 = fmaxf(fminf(hi1, hi2), fmaxf(lo1, lo2));

            // shared 3-level butterfly (8 lanes = 32 columns): rs + exact top-2
            #pragma unroll
            for (int o = 4; o > 0; o >>= 1) {
                rsl += __shfl_xor_sync(0xFFFFFFFFu, rsl, o);
                float om1 = __shfl_xor_sync(0xFFFFFFFFu, m1, o);
                float om2 = __shfl_xor_sync(0xFFFFFFFFu, m2, o);
                m2 = fmaxf(fminf(m1, om1), fmaxf(m2, om2));
                m1 = fmaxf(m1, om1);
            }

            // witness index: some lane's component equals m1 exactly
            int idx = -1;
            if (w.x == m1) idx = l8;
            if (w.y == m1) idx = l8 + 1;
            if (w.z == m1) idx = l8 + 2;
            if (w.w == m1) idx = l8 + 3;
            if (idx >= 0) s_bi[(r + k) * NBLK + g] = (unsigned char)idx;

            if ((lane & 7) == 0) {
                s_bm[(r + k) * NBLK + g]   = m1;
                s_bm2[(r + k) * NBLK + g]  = m2;
                s_rs32[(r + k) * NBLK + g] = rsl;
            }
        }
    }
    __syncthreads();

    // column sums -> L2-resident atomic accumulator (64 KB total)
    float* cs = g_colsum + (size_t)b * Q + 4 * t;
    atomicAdd(cs + 0, acc.x);
    atomicAdd(cs + 1, acc.y);
    atomicAdd(cs + 2, acc.z);
    atomicAdd(cs + 3, acc.w);

    // finish row sums: thread t<64 sums 32 partials of row t (rotated)
    if (t < RCHUNK) {
        float s = 0.f;
        #pragma unroll
        for (int i = 0; i < NBLK; ++i)
            s += s_rs32[t * NBLK + ((i + t) & (NBLK - 1))];
        g_rs[b * R + c * RCHUNK + t] = s;
    }

    // headers out: exact m1 (float) + packed (quantized m2 delta, witness)
    const size_t rowbase = (size_t)b * R + (size_t)c * RCHUNK;
    float4* gbm = reinterpret_cast<float4*>(g_bm + rowbase * NBLK);
    const float4* sb = reinterpret_cast<const float4*>(s_bm);
    gbm[t]       = sb[t];
    gbm[t + 256] = sb[t + 256];

    // pack 8 entries per thread: aux = (d << 8) | bi, d = floor((m1-m2)*32) sat
    {
        unsigned int pk[4];
        #pragma unroll
        for (int i = 0; i < 4; ++i) {
            int e0 = 8 * t + 2 * i;
            float d0f = (s_bm[e0] - s_bm2[e0]) * M2SCALE;
            float d1f = (s_bm[e0 + 1] - s_bm2[e0 + 1]) * M2SCALE;
            unsigned int d0 = min(255u, (unsigned int)d0f);   // floor: bound stays valid
            unsigned int d1 = min(255u, (unsigned int)d1f);
            unsigned int a0 = (d0 << 8) | s_bi[e0];
            unsigned int a1 = (d1 << 8) | s_bi[e0 + 1];
            pk[i] = a0 | (a1 << 16);
        }
        reinterpret_cast<uint4*>(g_aux + rowbase * NBLK)[t] =
            make_uint4(pk[0], pk[1], pk[2], pk[3]);
    }
}

// ---------------------------------------------------------------------------
// Kernel 2: Cref = log(colsum) from the L2-resident accumulator; per-32-col Cmin.
// ---------------------------------------------------------------------------
__global__ __launch_bounds__(256) void qatm_cred()
{
    const int b    = blockIdx.x >> 2;
    const int col  = ((blockIdx.x & 3) << 8) + threadIdx.x;
    const int lane = threadIdx.x & 31;

    float lg = __logf(g_colsum[b * Q + col]);
    g_creflog[b * Q + col] = lg;

    float mn = lg;
    #pragma unroll
    for (int o = 16; o > 0; o >>= 1)
        mn = fminf(mn, __shfl_xor_sync(0xFFFFFFFFu, mn, o));
    if (lane == 0)
        g_cmin[b * NBLK + (col >> 5)] = mn;
}

// ---------------------------------------------------------------------------
// Pass 2: warp per FOUR rows.
//   lb = max_j (cc*bm_j - Cref[witness_j])        (witness value exact)
//   block j scanned ONLY if cc*(bm_j - d_j/32) - Cmin_j > lb
//   (bm_j - d_j/32 >= true second max; all non-witness elements <= it).
// ---------------------------------------------------------------------------
__global__ __launch_bounds__(256) void qatm_p2(
    const float* __restrict__ x,
    const float* __restrict__ cr,
    const float* __restrict__ cq,
    float* __restrict__ out)
{
    const int wid  = threadIdx.x >> 5;
    const int lane = threadIdx.x & 31;
    const int row0 = (blockIdx.x * 8 + wid) * 4;
    const int b    = row0 >> 12;           // 4 consecutive rows share a batch

    const float cc = cr[0] + cq[0];
    const float* cl = g_creflog + (size_t)b * Q;

    // independent header loads for 4 rows
    const float cmin = __ldg(&g_cmin[b * NBLK + lane]);
    float bm0 = g_bm[(size_t)(row0 + 0) * NBLK + lane];
    float bm1 = g_bm[(size_t)(row0 + 1) * NBLK + lane];
    float bm2 = g_bm[(size_t)(row0 + 2) * NBLK + lane];
    float bm3 = g_bm[(size_t)(row0 + 3) * NBLK + lane];
    unsigned int a0 = g_aux[(size_t)(row0 + 0) * NBLK + lane];
    unsigned int a1 = g_aux[(size_t)(row0 + 1) * NBLK + lane];
    unsigned int a2 = g_aux[(size_t)(row0 + 2) * NBLK + lane];
    unsigned int a3 = g_aux[(size_t)(row0 + 3) * NBLK + lane];
    float rr = (lane < 4) ? __ldg(&g_rs[row0 + lane]) : 1.f;

    float cw0 = __ldg(cl + lane * 32 + (a0 & 255u));
    float cw1 = __ldg(cl + lane * 32 + (a1 & 255u));
    float cw2 = __ldg(cl + lane * 32 + (a2 & 255u));
    float cw3 = __ldg(cl + lane * 32 + (a3 & 255u));

    float s0 = bm0 - (float)(a0 >> 8) * M2INV;   // >= true second max
    float s1 = bm1 - (float)(a1 >> 8) * M2INV;
    float s2 = bm2 - (float)(a2 >> 8) * M2INV;
    float s3 = bm3 - (float)(a3 >> 8) * M2INV;

    // exact witness values -> lb
    float m0 = fmaf(cc, bm0, -cw0);
    float m1 = fmaf(cc, bm1, -cw1);
    float m2 = fmaf(cc, bm2, -cw2);
    float m3 = fmaf(cc, bm3, -cw3);
    #pragma unroll
    for (int o = 16; o > 0; o >>= 1) {
        m0 = fmaxf(m0, __shfl_xor_sync(0xFFFFFFFFu, m0, o));
        m1 = fmaxf(m1, __shfl_xor_sync(0xFFFFFFFFu, m1, o));
        m2 = fmaxf(m2, __shfl_xor_sync(0xFFFFFFFFu, m2, o));
        m3 = fmaxf(m3, __shfl_xor_sync(0xFFFFFFFFu, m3, o));
    }

    unsigned k0 = __ballot_sync(0xFFFFFFFFu, fmaf(cc, s0, -cmin) > m0);
    unsigned k1 = __ballot_sync(0xFFFFFFFFu, fmaf(cc, s1, -cmin) > m1);
    unsigned k2 = __ballot_sync(0xFFFFFFFFu, fmaf(cc, s2, -cmin) > m2);
    unsigned k3 = __ballot_sync(0xFFFFFFFFu, fmaf(cc, s3, -cmin) > m3);

    const float* px0 = x + (size_t)(row0 + 0) * Q;
    const float* px1 = x + (size_t)(row0 + 1) * Q;
    const float* px2 = x + (size_t)(row0 + 2) * Q;
    const float* px3 = x + (size_t)(row0 + 3) * Q;

    while (k0 | k1 | k2 | k3) {
        int j0 = -1, j1 = -1, j2 = -1, j3 = -1;
        if (k0) { j0 = __ffs(k0) - 1; k0 &= k0 - 1; }
        if (k1) { j1 = __ffs(k1) - 1; k1 &= k1 - 1; }
        if (k2) { j2 = __ffs(k2) - 1; k2 &= k2 - 1; }
        if (k3) { j3 = __ffs(k3) - 1; k3 &= k3 - 1; }

        float b0 = (j0 >= 0) ? __ldcs(px0 + j0 * 32 + lane) : 0.f;
        float b1 = (j1 >= 0) ? __ldcs(px1 + j1 * 32 + lane) : 0.f;
        float b2 = (j2 >= 0) ? __ldcs(px2 + j2 * 32 + lane) : 0.f;
        float b3 = (j3 >= 0) ? __ldcs(px3 + j3 * 32 + lane) : 0.f;
        float c0 = (j0 >= 0) ? __ldg(cl + j0 * 32 + lane) : 0.f;
        float c1 = (j1 >= 0) ? __ldg(cl + j1 * 32 + lane) : 0.f;
        float c2 = (j2 >= 0) ? __ldg(cl + j2 * 32 + lane) : 0.f;
        float c3 = (j3 >= 0) ? __ldg(cl + j3 * 32 + lane) : 0.f;

        if (j0 >= 0) m0 = fmaxf(m0, fmaf(cc, b0, -c0));
        if (j1 >= 0) m1 = fmaxf(m1, fmaf(cc, b1, -c1));
        if (j2 >= 0) m2 = fmaxf(m2, fmaf(cc, b2, -c2));
        if (j3 >= 0) m3 = fmaxf(m3, fmaf(cc, b3, -c3));
    }

    #pragma unroll
    for (int o = 16; o > 0; o >>= 1) {
        m0 = fmaxf(m0, __shfl_xor_sync(0xFFFFFFFFu, m0, o));
        m1 = fmaxf(m1, __shfl_xor_sync(0xFFFFFFFFu, m1, o));
        m2 = fmaxf(m2, __shfl_xor_sync(0xFFFFFFFFu, m2, o));
        m3 = fmaxf(m3, __shfl_xor_sync(0xFFFFFFFFu, m3, o));
    }

    if (lane < 4) {
        float mm = (lane == 0) ? m0 : (lane == 1) ? m1 : (lane == 2) ? m2 : m3;
        out[row0 + lane] = __expf(0.5f * (mm - __logf(rr)));
    }
}

// ---------------------------------------------------------------------------
extern "C" void kernel_launch(void* const* d_in, const int* in_sizes, int n_in,
                              void* d_out, int out_size)
{
    const float* x  = (const float*)d_in[0];
    const float* cr = (const float*)d_in[1];
    const float* cq = (const float*)d_in[2];
    float* out = (float*)d_out;

    const int B = in_sizes[0] / (R * Q);   // 16

    qatm_zero<<<MAXB, 1024>>>();
    qatm_pass1<<<B * NCHUNK, 256>>>(x, cr, cq);
    qatm_cred<<<B * 4, 256>>>();
    qatm_p2<<<B * R / 32, 256>>>(x, cr, cq, out);
}